// round 4
// baseline (speedup 1.0000x reference)
#include <cuda_runtime.h>
#include <math.h>

// ---------------- problem dims ----------------
#define B_    4
#define C_    256
#define RES_  128
#define HW_   16384
#define WF_   65
#define F_    8320       // 128*65, layout [u][k]
#define NB_   6

// ---------------- device scratch (allocation-free) ----------------
__device__ float  g_xT[B_*C_*HW_];        // (B,C,H,W)
__device__ float2 g_Xf[B_*C_*F_];         // forward spectrum
__device__ float2 g_Xmap[B_*C_*F_];       // channel-mixed low spectrum (mask region valid)
__device__ float  g_spec[B_*C_*HW_];      // irfft + conv, (B,C,HW)
__device__ float  g_specT[B_*C_*HW_];     // transposed to (B,HW,C)
__device__ float  g_bandsum[B_*C_*NB_];
__device__ float  g_alpha[B_*C_*NB_];
__device__ float  g_cnt[NB_];
__device__ int    g_mask[2];              // Ku (H thresh), Kw (W thresh)
__device__ float  g_linT[C_*C_];          // lin_w transposed: [d][c]

// Exact float32 replica of the numpy radial band partition.
__device__ __forceinline__ int band_id(int u, int k) {
    float yy = __fdiv_rn((float)u, 127.0f);
    float xx = __fdiv_rn((float)k, 64.0f);
    float r  = __fsqrt_rn(__fadd_rn(__fmul_rn(yy, yy), __fmul_rn(xx, xx)));
    float den = __fadd_rn(__fsqrt_rn(2.0f), 1e-8f);
    r = __fdiv_rn(r, den);
    int b = (int)floorf(__fmul_rn(r, 6.0f));
    return b > 5 ? 5 : b;
}

// ---------------- K0: counts + mask dims ----------------
__global__ void k_init(const float* kx, const float* ky) {
    __shared__ int cnt[NB_];
    int t = threadIdx.x;
    if (t < NB_) cnt[t] = 0;
    __syncthreads();
    for (int f = t; f < F_; f += blockDim.x) {
        int u = f / WF_, k = f % WF_;
        atomicAdd(&cnt[band_id(u, k)], 1);
    }
    __syncthreads();
    if (t < NB_) g_cnt[t] = fmaxf((float)cnt[t], 1.0f);
    if (t == 0) {
        float sx = 1.0f / (1.0f + expf(-kx[0]));
        float sy = 1.0f / (1.0f + expf(-ky[0]));
        int Ku = (int)floorf(sx * 128.0f); Ku = Ku < 0 ? 0 : (Ku > 128 ? 128 : Ku);
        int Kw = (int)floorf(sy * 65.0f);  Kw = Kw < 0 ? 0 : (Kw > 65  ? 65  : Kw);
        g_mask[0] = Ku; g_mask[1] = Kw;
    }
}

// ---------------- K0b: transpose lin_w -> g_linT ----------------
__global__ void k_linT(const float* __restrict__ lw) {
    __shared__ float tile[32][33];
    int c0 = blockIdx.x * 32, d0 = blockIdx.y * 32;
    for (int i = threadIdx.y; i < 32; i += 8)
        tile[i][threadIdx.x] = lw[(c0 + i) * C_ + d0 + threadIdx.x];
    __syncthreads();
    for (int i = threadIdx.y; i < 32; i += 8)
        g_linT[(d0 + i) * C_ + c0 + threadIdx.x] = tile[threadIdx.x][i];
}

// ---------------- K_tr: x (B,HW,C) -> g_xT (B,C,HW) ----------------
__global__ void k_xT(const float* __restrict__ x) {
    __shared__ float tile[32][33];
    int p0 = blockIdx.x * 32, c0 = blockIdx.y * 32, b = blockIdx.z;
    const float* xb = x + (size_t)b * HW_ * C_;
    for (int i = threadIdx.y; i < 32; i += 8)
        tile[i][threadIdx.x] = xb[(size_t)(p0 + i) * C_ + c0 + threadIdx.x];
    __syncthreads();
    float* o = g_xT + (size_t)b * C_ * HW_;
    for (int i = threadIdx.y; i < 32; i += 8)
        o[(size_t)(c0 + i) * HW_ + p0 + threadIdx.x] = tile[threadIdx.x][i];
}

// ---------------- K1: forward rfft2 per (b,c) + band sums ----------------
// dyn smem: sx[128*129] f32 | sy[128*66] f2 | tw[128] f2   = 134656 B
__global__ void __launch_bounds__(512) k_fwd() {
    extern __shared__ float sm1[];
    float*  sx = sm1;                          // 128*129
    float2* sy = (float2*)(sx + 128 * 129);    // 128*66
    float2* tw = sy + 128 * 66;                // 128
    __shared__ float sbs[NB_];

    int tid = threadIdx.x;
    if (tid < 128) {
        float s, c;
        sincospif((float)tid * (1.0f / 64.0f), &s, &c);
        tw[tid] = make_float2(c, s);           // e^{+2pi i t/128}
    }
    if (tid < NB_) sbs[tid] = 0.0f;

    int bc = blockIdx.x;
    const float* img = g_xT + (size_t)bc * HW_;
    for (int i = tid; i < HW_; i += 512) {
        int r = i >> 7, w = i & 127;
        sx[r * 129 + w] = img[i];
    }
    __syncthreads();

    // stage 1: row rDFT. Y[row][k] = sum_w x[row][w] e^{-2pi i wk/128}
    for (int idx = tid; idx < WF_ * 128; idx += 512) {
        int k = idx >> 7, row = idx & 127;
        float ar0 = 0.f, ai0 = 0.f, ar1 = 0.f, ai1 = 0.f;
        const float* xr = sx + row * 129;
        #pragma unroll 8
        for (int w = 0; w < 128; w += 2) {
            float v0 = xr[w];     float2 t0 = tw[(w * k) & 127];
            float v1 = xr[w + 1]; float2 t1 = tw[((w + 1) * k) & 127];
            ar0 += v0 * t0.x; ai0 -= v0 * t0.y;
            ar1 += v1 * t1.x; ai1 -= v1 * t1.y;
        }
        sy[row * 66 + k] = make_float2(ar0 + ar1, ai0 + ai1);
    }
    __syncthreads();

    // stage 2: column DFT + |Z| band sums.  Z[u][k] = sum_h Y[h][k] e^{-2pi i hu/128}
    float acc6[NB_] = {0, 0, 0, 0, 0, 0};
    float2* out = g_Xf + (size_t)bc * F_;
    for (int idx = tid; idx < F_; idx += 512) {
        int u = idx / WF_, k = idx % WF_;
        float zr0 = 0.f, zi0 = 0.f, zr1 = 0.f, zi1 = 0.f;
        #pragma unroll 8
        for (int h = 0; h < 128; h += 2) {
            float2 y0 = sy[h * 66 + k];       float2 t0 = tw[(h * u) & 127];
            float2 y1 = sy[(h + 1) * 66 + k]; float2 t1 = tw[((h + 1) * u) & 127];
            zr0 += y0.x * t0.x + y0.y * t0.y;
            zi0 += y0.y * t0.x - y0.x * t0.y;
            zr1 += y1.x * t1.x + y1.y * t1.y;
            zi1 += y1.y * t1.x - y1.x * t1.y;
        }
        float zr = (zr0 + zr1) * (1.0f / 128.0f);
        float zi = (zi0 + zi1) * (1.0f / 128.0f);
        out[idx] = make_float2(zr, zi);
        float mag = sqrtf(zr * zr + zi * zi);
        int bid = band_id(u, k);
        #pragma unroll
        for (int n = 0; n < NB_; ++n) acc6[n] += (bid == n) ? mag : 0.0f;
    }
    __syncthreads();
    #pragma unroll
    for (int n = 0; n < NB_; ++n) atomicAdd(&sbs[n], acc6[n]);
    __syncthreads();
    if (tid < NB_) g_bandsum[bc * NB_ + tid] = sbs[tid];
}

// ---------------- K2: gate MLP (one thread per (b,c)) ----------------
__global__ void k_gate(const float* __restrict__ w1, const float* __restrict__ b1,
                       const float* __restrict__ w2, const float* __restrict__ b2) {
    int bc = blockIdx.x * blockDim.x + threadIdx.x;
    if (bc >= B_ * C_) return;
    float means[NB_];
    #pragma unroll
    for (int n = 0; n < NB_; ++n)
        means[n] = g_bandsum[bc * NB_ + n] / (g_cnt[n] + 1e-6f);
    float acc[NB_] = {0, 0, 0, 0, 0, 0};
    for (int j = 0; j < 128; ++j) {
        float h = b1[j];
        #pragma unroll
        for (int n = 0; n < NB_; ++n) h += means[n] * w1[j * NB_ + n];
        h = fmaxf(h, 0.0f);
        #pragma unroll
        for (int n = 0; n < NB_; ++n) acc[n] += w2[n * 128 + j] * h;
    }
    #pragma unroll
    for (int n = 0; n < NB_; ++n)
        g_alpha[bc * NB_ + n] = 1.0f / (1.0f + expf(-(acc[n] + b2[n])));
}

// ---------------- K3: complex channel-mix GEMM over masked freqs ----------------
// block: 64 c x 64 fm tile, 256 threads, 4x4 complex micro-tile.
__global__ void __launch_bounds__(256) k_mix(const float* __restrict__ wr,
                                             const float* __restrict__ wi) {
    __shared__ float swr[16][64], swi[16][64], sxr[16][64], sxi[16][64];
    int Ku = g_mask[0], Kw = g_mask[1];
    int Fm = Ku * Kw;
    int fm0 = blockIdx.x * 64;
    if (fm0 >= Fm) return;
    int c0 = blockIdx.y * 64;
    int b  = blockIdx.z;
    int tid = threadIdx.x;
    int cg = tid >> 4, fg = tid & 15;

    float ar[4][4], ai[4][4];
    #pragma unroll
    for (int j = 0; j < 4; ++j)
        #pragma unroll
        for (int i = 0; i < 4; ++i) { ar[j][i] = 0.f; ai[j][i] = 0.f; }

    int cl = tid >> 2, q = tid & 3;
    int ddl = tid >> 4; int f4 = (tid & 15) * 4;

    for (int d0 = 0; d0 < C_; d0 += 16) {
        float4 vr = *(const float4*)(wr + (size_t)(c0 + cl) * C_ + d0 + q * 4);
        float4 vi = *(const float4*)(wi + (size_t)(c0 + cl) * C_ + d0 + q * 4);
        swr[q * 4 + 0][cl] = vr.x; swr[q * 4 + 1][cl] = vr.y;
        swr[q * 4 + 2][cl] = vr.z; swr[q * 4 + 3][cl] = vr.w;
        swi[q * 4 + 0][cl] = vi.x; swi[q * 4 + 1][cl] = vi.y;
        swi[q * 4 + 2][cl] = vi.z; swi[q * 4 + 3][cl] = vi.w;
        const float2* xrow = g_Xf + (size_t)(b * C_ + d0 + ddl) * F_;
        #pragma unroll
        for (int ii = 0; ii < 4; ++ii) {
            int fm = fm0 + f4 + ii;
            float2 z = make_float2(0.f, 0.f);
            if (fm < Fm) {
                int u = fm / Kw, k = fm - u * Kw;
                z = xrow[u * WF_ + k];
            }
            sxr[ddl][f4 + ii] = z.x;
            sxi[ddl][f4 + ii] = z.y;
        }
        __syncthreads();
        #pragma unroll
        for (int dd = 0; dd < 16; ++dd) {
            float4 w4r = *(const float4*)&swr[dd][cg * 4];
            float4 w4i = *(const float4*)&swi[dd][cg * 4];
            float4 x4r = *(const float4*)&sxr[dd][fg * 4];
            float4 x4i = *(const float4*)&sxi[dd][fg * 4];
            float wrv[4] = {w4r.x, w4r.y, w4r.z, w4r.w};
            float wiv[4] = {w4i.x, w4i.y, w4i.z, w4i.w};
            float xrv[4] = {x4r.x, x4r.y, x4r.z, x4r.w};
            float xiv[4] = {x4i.x, x4i.y, x4i.z, x4i.w};
            #pragma unroll
            for (int j = 0; j < 4; ++j)
                #pragma unroll
                for (int i = 0; i < 4; ++i) {
                    ar[j][i] += wrv[j] * xrv[i] - wiv[j] * xiv[i];
                    ai[j][i] += wrv[j] * xiv[i] + wiv[j] * xrv[i];
                }
        }
        __syncthreads();
    }
    #pragma unroll
    for (int j = 0; j < 4; ++j) {
        int c = c0 + cg * 4 + j;
        float2* orow = g_Xmap + (size_t)(b * C_ + c) * F_;
        #pragma unroll
        for (int i = 0; i < 4; ++i) {
            int fm = fm0 + fg * 4 + i;
            if (fm < Fm) {
                int u = fm / Kw, k = fm - u * Kw;
                orow[u * WF_ + k] = make_float2(ar[j][i], ai[j][i]);
            }
        }
    }
}

// ---------------- K4: fuse + irfft2 + depthwise conv per (b,c) ----------------
// dyn smem: sx[128*129] f32 | sz[128*66] f2 | syh[128*66] f2 | tw[128] f2 = 202240 B
__global__ void __launch_bounds__(512) k_inv(const float* __restrict__ conv_w) {
    extern __shared__ float sm4[];
    float*  sx  = sm4;                          // image for conv
    float2* sz  = (float2*)(sx + 128 * 129);
    float2* syh = sz + 128 * 66;
    float2* tw  = syh + 128 * 66;
    __shared__ float sal[NB_];

    int tid = threadIdx.x;
    int bc  = blockIdx.x;
    int c   = bc & 255;

    if (tid < 128) {
        float s, cc;
        sincospif((float)tid * (1.0f / 64.0f), &s, &cc);
        tw[tid] = make_float2(cc, s);
    }
    if (tid < NB_) sal[tid] = g_alpha[bc * NB_ + tid];

    float cw[9];
    #pragma unroll
    for (int j = 0; j < 9; ++j) cw[j] = conv_w[c * 9 + j];

    const float* img = g_xT + (size_t)bc * HW_;
    for (int i = tid; i < HW_; i += 512) {
        int r = i >> 7, w = i & 127;
        sx[r * 129 + w] = img[i];
    }
    __syncthreads();

    int Ku = g_mask[0], Kw = g_mask[1];
    const float2* Xf = g_Xf   + (size_t)bc * F_;
    const float2* Xm = g_Xmap + (size_t)bc * F_;
    for (int idx = tid; idx < F_; idx += 512) {
        int u = idx / WF_, k = idx % WF_;
        float a = sal[band_id(u, k)];
        float2 v;
        if (u < Ku && k < Kw) {
            float2 m = Xm[idx];
            v = make_float2(a * m.x, a * m.y);
        } else {
            float2 z = Xf[idx];
            float om = 1.0f - a;
            v = make_float2(om * z.x, om * z.y);
        }
        sz[u * 66 + k] = v;
    }
    __syncthreads();

    // stage A: Yh[h][k] = sum_u Z[u][k] e^{+2pi i hu/128}
    for (int idx = tid; idx < 128 * WF_; idx += 512) {
        int h = idx / WF_, k = idx % WF_;
        float yr0 = 0.f, yi0 = 0.f, yr1 = 0.f, yi1 = 0.f;
        #pragma unroll 8
        for (int u = 0; u < 128; u += 2) {
            float2 z0 = sz[u * 66 + k];       float2 t0 = tw[(h * u) & 127];
            float2 z1 = sz[(u + 1) * 66 + k]; float2 t1 = tw[(h * (u + 1)) & 127];
            yr0 += z0.x * t0.x - z0.y * t0.y;
            yi0 += z0.x * t0.y + z0.y * t0.x;
            yr1 += z1.x * t1.x - z1.y * t1.y;
            yi1 += z1.x * t1.y + z1.y * t1.x;
        }
        syh[h * 66 + k] = make_float2(yr0 + yr1, yi0 + yi1);
    }
    __syncthreads();

    // stage B: Hermitian row inverse + conv
    float* outp = g_spec + (size_t)bc * HW_;
    for (int idx = tid; idx < HW_; idx += 512) {
        int h = idx >> 7, w = idx & 127;
        const float2* yrow = syh + h * 66;
        float2 y0 = yrow[0], y64 = yrow[64];
        float acc = y0.x + ((w & 1) ? -y64.x : y64.x);
        float s0 = 0.f, s1 = 0.f;
        #pragma unroll 7
        for (int k = 1; k < 64; k += 2) {
            float2 ya = yrow[k];     float2 ta = tw[(w * k) & 127];
            float2 yb = yrow[k + 1]; float2 tb = tw[(w * (k + 1)) & 127];
            s0 += ya.x * ta.x - ya.y * ta.y;
            if (k + 1 < 64) s1 += yb.x * tb.x - yb.y * tb.y;
        }
        acc += 2.0f * (s0 + s1);
        acc *= (1.0f / 128.0f);
        // depthwise 3x3, zero pad
        float cv = 0.f;
        #pragma unroll
        for (int di = -1; di <= 1; ++di) {
            int hh = h + di;
            if (hh < 0 || hh >= 128) continue;
            #pragma unroll
            for (int dj = -1; dj <= 1; ++dj) {
                int ww = w + dj;
                if (ww < 0 || ww >= 128) continue;
                cv += sx[hh * 129 + ww] * cw[(di + 1) * 3 + (dj + 1)];
            }
        }
        outp[idx] = acc + cv;
    }
}

// ---------------- K4b: g_spec (B,C,HW) -> g_specT (B,HW,C) ----------------
__global__ void k_specT() {
    __shared__ float tile[32][33];
    int p0 = blockIdx.x * 32, c0 = blockIdx.y * 32, b = blockIdx.z;
    for (int i = threadIdx.y; i < 32; i += 8)
        tile[i][threadIdx.x] = g_spec[(size_t)(b * C_ + c0 + i) * HW_ + p0 + threadIdx.x];
    __syncthreads();
    for (int i = threadIdx.y; i < 32; i += 8)
        g_specT[((size_t)b * HW_ + p0 + i) * C_ + c0 + threadIdx.x] = tile[threadIdx.x][i];
}

// ---------------- K5: pointwise GEMM + adds + conditional LN ----------------
// block: 64 pixels x 256 channels; 256 threads; 8x8 micro.
__global__ void __launch_bounds__(256) k_out(
    const float* __restrict__ x, const float* __restrict__ lin_b,
    const float* __restrict__ time_, const float* __restrict__ nww,
    const float* __restrict__ nwb, const float* __restrict__ nbw,
    const float* __restrict__ nbb, float* __restrict__ out) {
    __shared__ float sa[16 * 64];
    __shared__ float sb[16 * 256];
    int b = blockIdx.y;
    int p0 = blockIdx.x * 64;
    int tid = threadIdx.x;
    int pg = tid >> 5;         // warp id -> 8 pixels
    int cg = tid & 31;         // lane -> channels {4cg..4cg+3} U {128+4cg..+3}

    float acc[8][8];
    #pragma unroll
    for (int i = 0; i < 8; ++i)
        #pragma unroll
        for (int j = 0; j < 8; ++j) acc[i][j] = 0.f;

    const float* xb = x + ((size_t)b * HW_ + p0) * C_;
    int arow = tid >> 2, aq = tid & 3;

    for (int d0 = 0; d0 < C_; d0 += 16) {
        float4 v = *(const float4*)(xb + (size_t)arow * C_ + d0 + aq * 4);
        sa[(aq * 4 + 0) * 64 + arow] = v.x;
        sa[(aq * 4 + 1) * 64 + arow] = v.y;
        sa[(aq * 4 + 2) * 64 + arow] = v.z;
        sa[(aq * 4 + 3) * 64 + arow] = v.w;
        const float4* src = (const float4*)(g_linT + (size_t)d0 * C_);
        float4* dst = (float4*)sb;
        #pragma unroll
        for (int q = 0; q < 4; ++q) dst[tid * 4 + q] = src[tid * 4 + q];
        __syncthreads();
        #pragma unroll
        for (int dd = 0; dd < 16; ++dd) {
            float4 a0 = *(const float4*)(sa + dd * 64 + pg * 8);
            float4 a1 = *(const float4*)(sa + dd * 64 + pg * 8 + 4);
            float4 b0 = *(const float4*)(sb + dd * 256 + cg * 4);
            float4 b1 = *(const float4*)(sb + dd * 256 + 128 + cg * 4);
            float av[8] = {a0.x, a0.y, a0.z, a0.w, a1.x, a1.y, a1.z, a1.w};
            float bv[8] = {b0.x, b0.y, b0.z, b0.w, b1.x, b1.y, b1.z, b1.w};
            #pragma unroll
            for (int i = 0; i < 8; ++i)
                #pragma unroll
                for (int j = 0; j < 8; ++j) acc[i][j] += av[i] * bv[j];
        }
        __syncthreads();
    }

    int cA = cg * 4, cB = 128 + cg * 4;
    float tb = time_[b];
    float lb[8], wj[8], bj[8];
    #pragma unroll
    for (int j = 0; j < 8; ++j) {
        int cc = (j < 4) ? (cA + j) : (cB + j - 4);
        lb[j] = lin_b[cc];
        wj[j] = tb * nww[cc] + nwb[cc];
        bj[j] = tb * nbw[cc] + nbb[cc];
    }

    #pragma unroll
    for (int i = 0; i < 8; ++i) {
        int p = p0 + pg * 8 + i;
        const float* sp = g_specT + ((size_t)b * HW_ + p) * C_;
        float4 s0 = *(const float4*)(sp + cA);
        float4 s1 = *(const float4*)(sp + cB);
        float sv[8] = {s0.x, s0.y, s0.z, s0.w, s1.x, s1.y, s1.z, s1.w};
        float sum = 0.f, sq = 0.f;
        #pragma unroll
        for (int j = 0; j < 8; ++j) {
            acc[i][j] += lb[j] + sv[j];
            sum += acc[i][j];
            sq  += acc[i][j] * acc[i][j];
        }
        #pragma unroll
        for (int off = 16; off > 0; off >>= 1) {
            sum += __shfl_xor_sync(0xffffffffu, sum, off);
            sq  += __shfl_xor_sync(0xffffffffu, sq,  off);
        }
        float mean = sum * (1.0f / 256.0f);
        float var  = sq * (1.0f / 256.0f) - mean * mean;
        float r    = 1.0f / sqrtf(var + 1e-5f);
        float o[8];
        #pragma unroll
        for (int j = 0; j < 8; ++j)
            o[j] = wj[j] * ((acc[i][j] - mean) * r) + bj[j];
        float* op = out + ((size_t)b * HW_ + p) * C_;
        *(float4*)(op + cA) = make_float4(o[0], o[1], o[2], o[3]);
        *(float4*)(op + cB) = make_float4(o[4], o[5], o[6], o[7]);
    }
}

// ---------------- launcher ----------------
extern "C" void kernel_launch(void* const* d_in, const int* in_sizes, int n_in,
                              void* d_out, int out_size) {
    const float* x      = (const float*)d_in[0];
    const float* time_  = (const float*)d_in[1];
    const float* w_real = (const float*)d_in[2];
    const float* w_imag = (const float*)d_in[3];
    const float* conv_w = (const float*)d_in[4];
    const float* lin_w  = (const float*)d_in[5];
    const float* lin_b  = (const float*)d_in[6];
    const float* mlp_w1 = (const float*)d_in[7];
    const float* mlp_b1 = (const float*)d_in[8];
    const float* mlp_w2 = (const float*)d_in[9];
    const float* mlp_b2 = (const float*)d_in[10];
    const float* nww    = (const float*)d_in[11];
    const float* nwb    = (const float*)d_in[12];
    const float* nbw    = (const float*)d_in[13];
    const float* nbb    = (const float*)d_in[14];
    const float* kx     = (const float*)d_in[15];
    const float* ky     = (const float*)d_in[16];
    float* out = (float*)d_out;

    const int SM1 = 128 * 129 * 4 + 128 * 66 * 8 + 128 * 8;            // 134656
    const int SM4 = 128 * 129 * 4 + 2 * (128 * 66 * 8) + 128 * 8;      // 202240
    cudaFuncSetAttribute(k_fwd, cudaFuncAttributeMaxDynamicSharedMemorySize, SM1);
    cudaFuncSetAttribute(k_inv, cudaFuncAttributeMaxDynamicSharedMemorySize, SM4);

    k_init<<<1, 256>>>(kx, ky);
    k_linT<<<dim3(8, 8), dim3(32, 8)>>>(lin_w);
    k_xT<<<dim3(512, 8, 4), dim3(32, 8)>>>(x);
    k_fwd<<<B_ * C_, 512, SM1>>>();
    k_gate<<<4, 256>>>(mlp_w1, mlp_b1, mlp_w2, mlp_b2);
    k_mix<<<dim3(130, 4, 4), 256>>>(w_real, w_imag);
    k_inv<<<B_ * C_, 512, SM4>>>(conv_w);
    k_specT<<<dim3(512, 8, 4), dim3(32, 8)>>>();
    k_out<<<dim3(256, 4), 256>>>(x, lin_b, time_, nww, nwb, nbw, nbb, out);
}

// round 5
// speedup vs baseline: 2.8072x; 2.8072x over previous
#include <cuda_runtime.h>
#include <math.h>

// ---------------- problem dims ----------------
#define B_    4
#define C_    256
#define RES_  128
#define HW_   16384
#define WF_   65
#define F_    8320       // 65*128, layout [k][u]  (idx = k*128 + u)
#define NB_   6

// ---------------- device scratch (allocation-free) ----------------
__device__ float  g_xT[B_*C_*HW_];        // (B,C,H,W)
__device__ float2 g_Xf[B_*C_*F_];         // forward spectrum  [k][u]
__device__ float2 g_Xmap[B_*C_*F_];       // channel-mixed low spectrum (mask region valid)
__device__ float  g_spec[B_*C_*HW_];      // irfft + conv, (B,C,HW)
__device__ float  g_specT[B_*C_*HW_];     // transposed to (B,HW,C)
__device__ float  g_bandsum[B_*C_*NB_];
__device__ float  g_alpha[B_*C_*NB_];
__device__ float  g_cnt[NB_];
__device__ int    g_mask[2];              // Ku (H thresh), Kw (W thresh)
__device__ float  g_linT[C_*C_];          // lin_w transposed: [d][c]
__device__ unsigned char g_bid[F_];       // band id table, [k][u]

// Exact float32 replica of the numpy radial band partition.
__device__ __forceinline__ int band_id(int u, int k) {
    float yy = __fdiv_rn((float)u, 127.0f);
    float xx = __fdiv_rn((float)k, 64.0f);
    float r  = __fsqrt_rn(__fadd_rn(__fmul_rn(yy, yy), __fmul_rn(xx, xx)));
    float den = __fadd_rn(__fsqrt_rn(2.0f), 1e-8f);
    r = __fdiv_rn(r, den);
    int b = (int)floorf(__fmul_rn(r, 6.0f));
    return b > 5 ? 5 : b;
}

// ---------------- warp-cooperative 128-pt Stockham FFT (DIF, natural order out) ---
// tw[t] = exp(-2*pi*i*t/128), t in [0,64). inv=true conjugates twiddles.
// src data in b0 (128 float2); returns pointer to buffer holding the result (=b1).
__device__ __forceinline__ float2* warp_fft128(float2* b0, float2* b1,
                                               const float2* __restrict__ tw,
                                               int lane, bool inv) {
    float2* src = b0; float2* dst = b1;
#pragma unroll
    for (int st = 0; st < 7; ++st) {
        const int s = 1 << st;
#pragma unroll
        for (int h = 0; h < 2; ++h) {
            int j  = lane + (h << 5);          // butterfly index 0..63
            float2 a = src[j];
            float2 b = src[j + 64];
            int tb = j & ~(s - 1);             // twiddle index = p*s
            int od = j + tb;                   // q + 2*s*p
            float2 w = tw[tb];
            float wy = inv ? -w.y : w.y;
            dst[od] = make_float2(a.x + b.x, a.y + b.y);
            float dx = a.x - b.x, dy = a.y - b.y;
            dst[od + s] = make_float2(dx * w.x - dy * wy, dx * wy + dy * w.x);
        }
        __syncwarp();
        float2* t = src; src = dst; dst = t;
    }
    return src;   // 7 swaps -> result lives in b1
}

// ---------------- K0: counts + band table + mask dims ----------------
__global__ void k_init(const float* kx, const float* ky) {
    __shared__ int cnt[NB_];
    int t = threadIdx.x;
    if (t < NB_) cnt[t] = 0;
    __syncthreads();
    for (int idx = t; idx < F_; idx += blockDim.x) {
        int k = idx >> 7, u = idx & 127;
        int b = band_id(u, k);
        g_bid[idx] = (unsigned char)b;
        atomicAdd(&cnt[b], 1);
    }
    __syncthreads();
    if (t < NB_) g_cnt[t] = fmaxf((float)cnt[t], 1.0f);
    if (t == 0) {
        float sx = 1.0f / (1.0f + expf(-kx[0]));
        float sy = 1.0f / (1.0f + expf(-ky[0]));
        int Ku = (int)floorf(sx * 128.0f); Ku = Ku < 0 ? 0 : (Ku > 128 ? 128 : Ku);
        int Kw = (int)floorf(sy * 65.0f);  Kw = Kw < 0 ? 0 : (Kw > 65  ? 65  : Kw);
        g_mask[0] = Ku; g_mask[1] = Kw;
    }
}

// ---------------- K0b: transpose lin_w -> g_linT ----------------
__global__ void k_linT(const float* __restrict__ lw) {
    __shared__ float tile[32][33];
    int c0 = blockIdx.x * 32, d0 = blockIdx.y * 32;
    for (int i = threadIdx.y; i < 32; i += 8)
        tile[i][threadIdx.x] = lw[(c0 + i) * C_ + d0 + threadIdx.x];
    __syncthreads();
    for (int i = threadIdx.y; i < 32; i += 8)
        g_linT[(d0 + i) * C_ + c0 + threadIdx.x] = tile[threadIdx.x][i];
}

// ---------------- K_tr: x (B,HW,C) -> g_xT (B,C,HW) ----------------
__global__ void k_xT(const float* __restrict__ x) {
    __shared__ float tile[32][33];
    int p0 = blockIdx.x * 32, c0 = blockIdx.y * 32, b = blockIdx.z;
    const float* xb = x + (size_t)b * HW_ * C_;
    for (int i = threadIdx.y; i < 32; i += 8)
        tile[i][threadIdx.x] = xb[(size_t)(p0 + i) * C_ + c0 + threadIdx.x];
    __syncthreads();
    float* o = g_xT + (size_t)b * C_ * HW_;
    for (int i = threadIdx.y; i < 32; i += 8)
        o[(size_t)(c0 + i) * HW_ + p0 + threadIdx.x] = tile[threadIdx.x][i];
}

// ---------------- K1: forward rfft2 per (b,c) + band sums ----------------
// dyn smem: syr[128*65] | syi[128*65] | work[16*256 f2] | tw[64 f2]  = 99,840 B
__global__ void __launch_bounds__(512) k_fwd() {
    extern __shared__ float sm1[];
    float*  syr  = sm1;                          // [h*65 + k]
    float*  syi  = syr + 128 * 65;
    float2* work = (float2*)(syi + 128 * 65);    // 16 warps * 256
    float2* tw   = work + 16 * 256;              // 64
    __shared__ float sbs[NB_];

    int tid = threadIdx.x, warp = tid >> 5, lane = tid & 31;
    if (tid < 64) {
        float s, c;
        sincospif((float)tid * (1.0f / 64.0f), &s, &c);
        tw[tid] = make_float2(c, -s);            // e^{-2pi i t/128}
    }
    if (tid < NB_) sbs[tid] = 0.0f;
    __syncthreads();

    int bc = blockIdx.x;
    const float* img = g_xT + (size_t)bc * HW_;
    float2* w0 = work + warp * 256;
    float2* w1 = w0 + 128;

    // ---- row phase: pack 2 real rows -> 1 complex FFT, unpack half-spectra
    for (int rp = warp; rp < 64; rp += 16) {
        int ra = rp << 1, rb = ra + 1;
        const float* pa = img + ra * RES_;
        const float* pb = img + rb * RES_;
#pragma unroll
        for (int h = 0; h < 4; ++h) {
            int j = lane + (h << 5);
            w0[j] = make_float2(pa[j], pb[j]);
        }
        __syncwarp();
        float2* o = warp_fft128(w0, w1, tw, lane, false);
#pragma unroll
        for (int h = 0; h < 3; ++h) {
            int k = lane + (h << 5);
            if (k <= 64) {
                float2 zk = o[k];
                float2 zm = o[(128 - k) & 127];
                // A = row ra half-spectrum, B = row rb
                syr[ra * 65 + k] = 0.5f * (zk.x + zm.x);
                syi[ra * 65 + k] = 0.5f * (zk.y - zm.y);
                syr[rb * 65 + k] = 0.5f * (zk.y + zm.y);
                syi[rb * 65 + k] = 0.5f * (zm.x - zk.x);
            }
        }
        __syncwarp();
    }
    __syncthreads();

    // ---- column phase: 65 complex FFTs down the rows + band sums
    float acc6[NB_] = {0, 0, 0, 0, 0, 0};
    float2* out = g_Xf + (size_t)bc * F_;
    for (int k = warp; k < 65; k += 16) {
#pragma unroll
        for (int h = 0; h < 4; ++h) {
            int j = lane + (h << 5);
            w0[j] = make_float2(syr[j * 65 + k], syi[j * 65 + k]);
        }
        __syncwarp();
        float2* o = warp_fft128(w0, w1, tw, lane, false);
#pragma unroll
        for (int h = 0; h < 4; ++h) {
            int u = lane + (h << 5);
            float zr = o[u].x * (1.0f / 128.0f);
            float zi = o[u].y * (1.0f / 128.0f);
            out[k * 128 + u] = make_float2(zr, zi);
            float mag = sqrtf(zr * zr + zi * zi);
            int bid = g_bid[k * 128 + u];
#pragma unroll
            for (int n = 0; n < NB_; ++n) acc6[n] += (bid == n) ? mag : 0.0f;
        }
        __syncwarp();
    }
#pragma unroll
    for (int n = 0; n < NB_; ++n) atomicAdd(&sbs[n], acc6[n]);
    __syncthreads();
    if (tid < NB_) g_bandsum[bc * NB_ + tid] = sbs[tid];
}

// ---------------- K2: gate MLP (one thread per (b,c)) ----------------
__global__ void k_gate(const float* __restrict__ w1, const float* __restrict__ b1,
                       const float* __restrict__ w2, const float* __restrict__ b2) {
    int bc = blockIdx.x * blockDim.x + threadIdx.x;
    if (bc >= B_ * C_) return;
    float means[NB_];
    #pragma unroll
    for (int n = 0; n < NB_; ++n)
        means[n] = g_bandsum[bc * NB_ + n] / (g_cnt[n] + 1e-6f);
    float acc[NB_] = {0, 0, 0, 0, 0, 0};
    for (int j = 0; j < 128; ++j) {
        float h = b1[j];
        #pragma unroll
        for (int n = 0; n < NB_; ++n) h += means[n] * w1[j * NB_ + n];
        h = fmaxf(h, 0.0f);
        #pragma unroll
        for (int n = 0; n < NB_; ++n) acc[n] += w2[n * 128 + j] * h;
    }
    #pragma unroll
    for (int n = 0; n < NB_; ++n)
        g_alpha[bc * NB_ + n] = 1.0f / (1.0f + expf(-(acc[n] + b2[n])));
}

// ---------------- K3: complex channel-mix GEMM over masked freqs ----------------
// masked freq linearization: fm = k*Ku + u  (u fast -> coalesced [k][u] access)
__global__ void __launch_bounds__(256) k_mix(const float* __restrict__ wr,
                                             const float* __restrict__ wi) {
    __shared__ float swr[16][64], swi[16][64], sxr[16][64], sxi[16][64];
    int Ku = g_mask[0], Kw = g_mask[1];
    int Fm = Ku * Kw;
    int fm0 = blockIdx.x * 64;
    if (fm0 >= Fm) return;
    int c0 = blockIdx.y * 64;
    int b  = blockIdx.z;
    int tid = threadIdx.x;
    int cg = tid >> 4, fg = tid & 15;

    float ar[4][4], ai[4][4];
    #pragma unroll
    for (int j = 0; j < 4; ++j)
        #pragma unroll
        for (int i = 0; i < 4; ++i) { ar[j][i] = 0.f; ai[j][i] = 0.f; }

    int cl = tid >> 2, q = tid & 3;
    int ddl = tid >> 4; int f4 = (tid & 15) * 4;

    // hoist masked-freq -> memory-index mapping (loop-invariant over d0)
    int midx[4]; bool mok[4];
    #pragma unroll
    for (int ii = 0; ii < 4; ++ii) {
        int fm = fm0 + f4 + ii;
        mok[ii] = fm < Fm;
        if (mok[ii]) {
            int k = fm / Ku, u = fm - k * Ku;
            midx[ii] = k * 128 + u;
        } else midx[ii] = 0;
    }

    for (int d0 = 0; d0 < C_; d0 += 16) {
        float4 vr = *(const float4*)(wr + (size_t)(c0 + cl) * C_ + d0 + q * 4);
        float4 vi = *(const float4*)(wi + (size_t)(c0 + cl) * C_ + d0 + q * 4);
        swr[q * 4 + 0][cl] = vr.x; swr[q * 4 + 1][cl] = vr.y;
        swr[q * 4 + 2][cl] = vr.z; swr[q * 4 + 3][cl] = vr.w;
        swi[q * 4 + 0][cl] = vi.x; swi[q * 4 + 1][cl] = vi.y;
        swi[q * 4 + 2][cl] = vi.z; swi[q * 4 + 3][cl] = vi.w;
        const float2* xrow = g_Xf + (size_t)(b * C_ + d0 + ddl) * F_;
        #pragma unroll
        for (int ii = 0; ii < 4; ++ii) {
            float2 z = mok[ii] ? xrow[midx[ii]] : make_float2(0.f, 0.f);
            sxr[ddl][f4 + ii] = z.x;
            sxi[ddl][f4 + ii] = z.y;
        }
        __syncthreads();
        #pragma unroll
        for (int dd = 0; dd < 16; ++dd) {
            float4 w4r = *(const float4*)&swr[dd][cg * 4];
            float4 w4i = *(const float4*)&swi[dd][cg * 4];
            float4 x4r = *(const float4*)&sxr[dd][fg * 4];
            float4 x4i = *(const float4*)&sxi[dd][fg * 4];
            float wrv[4] = {w4r.x, w4r.y, w4r.z, w4r.w};
            float wiv[4] = {w4i.x, w4i.y, w4i.z, w4i.w};
            float xrv[4] = {x4r.x, x4r.y, x4r.z, x4r.w};
            float xiv[4] = {x4i.x, x4i.y, x4i.z, x4i.w};
            #pragma unroll
            for (int j = 0; j < 4; ++j)
                #pragma unroll
                for (int i = 0; i < 4; ++i) {
                    ar[j][i] += wrv[j] * xrv[i] - wiv[j] * xiv[i];
                    ai[j][i] += wrv[j] * xiv[i] + wiv[j] * xrv[i];
                }
        }
        __syncthreads();
    }
    #pragma unroll
    for (int j = 0; j < 4; ++j) {
        int c = c0 + cg * 4 + j;
        float2* orow = g_Xmap + (size_t)(b * C_ + c) * F_;
        #pragma unroll
        for (int i = 0; i < 4; ++i) {
            int fm = fm0 + fg * 4 + i;
            if (fm < Fm) {
                int k = fm / Ku, u = fm - k * Ku;
                orow[k * 128 + u] = make_float2(ar[j][i], ai[j][i]);
            }
        }
    }
}

// ---------------- K4: fuse + irfft2 + depthwise conv per (b,c) ----------------
// dyn smem: sx[128*129] | syr[128*65] | syi[128*65] | work[16*256 f2] | tw[64 f2]
//         = 66048 + 66560 + 33280(part of prev) ... total = 165,888 B
__global__ void __launch_bounds__(512) k_inv(const float* __restrict__ conv_w) {
    extern __shared__ float sm4[];
    float*  sx   = sm4;                          // 128*129 (image for conv)
    float*  syr  = sx + 128 * 129;
    float*  syi  = syr + 128 * 65;
    float2* work = (float2*)(syi + 128 * 65);
    float2* tw   = work + 16 * 256;
    __shared__ float sal[NB_];

    int tid = threadIdx.x, warp = tid >> 5, lane = tid & 31;
    int bc  = blockIdx.x;
    int c   = bc & 255;

    if (tid < 64) {
        float s, cc;
        sincospif((float)tid * (1.0f / 64.0f), &s, &cc);
        tw[tid] = make_float2(cc, -s);
    }
    if (tid < NB_) sal[tid] = g_alpha[bc * NB_ + tid];

    float cw[9];
    #pragma unroll
    for (int j = 0; j < 9; ++j) cw[j] = conv_w[c * 9 + j];

    const float* img = g_xT + (size_t)bc * HW_;
    for (int i = tid; i < HW_; i += 512) {
        int r = i >> 7, w = i & 127;
        sx[r * 129 + w] = img[i];
    }
    __syncthreads();

    int Ku = g_mask[0], Kw = g_mask[1];
    const float2* Xf = g_Xf   + (size_t)bc * F_;
    const float2* Xm = g_Xmap + (size_t)bc * F_;
    float2* w0 = work + warp * 256;
    float2* w1 = w0 + 128;

    // ---- column inverse: fuse alpha/mask on load, inverse FFT down rows
    for (int k = warp; k < 65; k += 16) {
        bool kin = (k < Kw);
#pragma unroll
        for (int h = 0; h < 4; ++h) {
            int u = lane + (h << 5);
            int idx = k * 128 + u;
            float a = sal[g_bid[idx]];
            float2 v;
            if (kin && u < Ku) {
                float2 m = Xm[idx];
                v = make_float2(a * m.x, a * m.y);
            } else {
                float2 z = Xf[idx];
                float om = 1.0f - a;
                v = make_float2(om * z.x, om * z.y);
            }
            w0[u] = v;
        }
        __syncwarp();
        float2* o = warp_fft128(w0, w1, tw, lane, true);
#pragma unroll
        for (int h = 0; h < 4; ++h) {
            int hh = lane + (h << 5);
            syr[hh * 65 + k] = o[hh].x;
            syi[hh * 65 + k] = o[hh].y;
        }
        __syncwarp();
    }
    __syncthreads();

    // ---- row inverse: Hermitian-pack two rows into one complex inverse FFT + conv
    float* outp = g_spec + (size_t)bc * HW_;
    for (int rp = warp; rp < 64; rp += 16) {
        int ra = rp << 1, rb = ra + 1;
        const float* yar_ = syr + ra * 65; const float* yai_ = syi + ra * 65;
        const float* ybr_ = syr + rb * 65; const float* ybi_ = syi + rb * 65;
#pragma unroll
        for (int h = 0; h < 4; ++h) {
            int j = lane + (h << 5);
            float2 z;
            if (j == 0) {
                z = make_float2(yar_[0], ybr_[0]);          // Im(DC) dropped
            } else if (j == 64) {
                z = make_float2(yar_[64], ybr_[64]);        // Im(Nyquist) dropped
            } else if (j < 64) {
                z = make_float2(yar_[j] - ybi_[j], yai_[j] + ybr_[j]);
            } else {
                int k = 128 - j;                            // conj extension
                z = make_float2(yar_[k] + ybi_[k], ybr_[k] - yai_[k]);
            }
            w0[j] = z;
        }
        __syncwarp();
        float2* o = warp_fft128(w0, w1, tw, lane, true);
#pragma unroll
        for (int h = 0; h < 4; ++h) {
            int w = lane + (h << 5);
            float va = o[w].x * (1.0f / 128.0f);
            float vb = o[w].y * (1.0f / 128.0f);
            // depthwise 3x3, zero pad, rows ra and rb
            float cva = 0.f, cvb = 0.f;
            #pragma unroll
            for (int di = -1; di <= 1; ++di) {
                #pragma unroll
                for (int dj = -1; dj <= 1; ++dj) {
                    int ww = w + dj;
                    if (ww < 0 || ww >= 128) continue;
                    float cwv = cw[(di + 1) * 3 + (dj + 1)];
                    int ha = ra + di;
                    if (ha >= 0 && ha < 128) cva += sx[ha * 129 + ww] * cwv;
                    int hb = rb + di;
                    if (hb >= 0 && hb < 128) cvb += sx[hb * 129 + ww] * cwv;
                }
            }
            outp[ra * 128 + w] = va + cva;
            outp[rb * 128 + w] = vb + cvb;
        }
        __syncwarp();
    }
}

// ---------------- K4b: g_spec (B,C,HW) -> g_specT (B,HW,C) ----------------
__global__ void k_specT() {
    __shared__ float tile[32][33];
    int p0 = blockIdx.x * 32, c0 = blockIdx.y * 32, b = blockIdx.z;
    for (int i = threadIdx.y; i < 32; i += 8)
        tile[i][threadIdx.x] = g_spec[(size_t)(b * C_ + c0 + i) * HW_ + p0 + threadIdx.x];
    __syncthreads();
    for (int i = threadIdx.y; i < 32; i += 8)
        g_specT[((size_t)b * HW_ + p0 + i) * C_ + c0 + threadIdx.x] = tile[threadIdx.x][i];
}

// ---------------- K5: pointwise GEMM + adds + conditional LN ----------------
__global__ void __launch_bounds__(256) k_out(
    const float* __restrict__ x, const float* __restrict__ lin_b,
    const float* __restrict__ time_, const float* __restrict__ nww,
    const float* __restrict__ nwb, const float* __restrict__ nbw,
    const float* __restrict__ nbb, float* __restrict__ out) {
    __shared__ float sa[16 * 64];
    __shared__ float sb[16 * 256];
    int b = blockIdx.y;
    int p0 = blockIdx.x * 64;
    int tid = threadIdx.x;
    int pg = tid >> 5;
    int cg = tid & 31;

    float acc[8][8];
    #pragma unroll
    for (int i = 0; i < 8; ++i)
        #pragma unroll
        for (int j = 0; j < 8; ++j) acc[i][j] = 0.f;

    const float* xb = x + ((size_t)b * HW_ + p0) * C_;
    int arow = tid >> 2, aq = tid & 3;

    for (int d0 = 0; d0 < C_; d0 += 16) {
        float4 v = *(const float4*)(xb + (size_t)arow * C_ + d0 + aq * 4);
        sa[(aq * 4 + 0) * 64 + arow] = v.x;
        sa[(aq * 4 + 1) * 64 + arow] = v.y;
        sa[(aq * 4 + 2) * 64 + arow] = v.z;
        sa[(aq * 4 + 3) * 64 + arow] = v.w;
        const float4* src = (const float4*)(g_linT + (size_t)d0 * C_);
        float4* dst = (float4*)sb;
        #pragma unroll
        for (int q = 0; q < 4; ++q) dst[tid * 4 + q] = src[tid * 4 + q];
        __syncthreads();
        #pragma unroll
        for (int dd = 0; dd < 16; ++dd) {
            float4 a0 = *(const float4*)(sa + dd * 64 + pg * 8);
            float4 a1 = *(const float4*)(sa + dd * 64 + pg * 8 + 4);
            float4 b0 = *(const float4*)(sb + dd * 256 + cg * 4);
            float4 b1 = *(const float4*)(sb + dd * 256 + 128 + cg * 4);
            float av[8] = {a0.x, a0.y, a0.z, a0.w, a1.x, a1.y, a1.z, a1.w};
            float bv[8] = {b0.x, b0.y, b0.z, b0.w, b1.x, b1.y, b1.z, b1.w};
            #pragma unroll
            for (int i = 0; i < 8; ++i)
                #pragma unroll
                for (int j = 0; j < 8; ++j) acc[i][j] += av[i] * bv[j];
        }
        __syncthreads();
    }

    int cA = cg * 4, cB = 128 + cg * 4;
    float tb = time_[b];
    float lb[8], wj[8], bj[8];
    #pragma unroll
    for (int j = 0; j < 8; ++j) {
        int cc = (j < 4) ? (cA + j) : (cB + j - 4);
        lb[j] = lin_b[cc];
        wj[j] = tb * nww[cc] + nwb[cc];
        bj[j] = tb * nbw[cc] + nbb[cc];
    }

    #pragma unroll
    for (int i = 0; i < 8; ++i) {
        int p = p0 + pg * 8 + i;
        const float* sp = g_specT + ((size_t)b * HW_ + p) * C_;
        float4 s0 = *(const float4*)(sp + cA);
        float4 s1 = *(const float4*)(sp + cB);
        float sv[8] = {s0.x, s0.y, s0.z, s0.w, s1.x, s1.y, s1.z, s1.w};
        float sum = 0.f, sq = 0.f;
        #pragma unroll
        for (int j = 0; j < 8; ++j) {
            acc[i][j] += lb[j] + sv[j];
            sum += acc[i][j];
            sq  += acc[i][j] * acc[i][j];
        }
        #pragma unroll
        for (int off = 16; off > 0; off >>= 1) {
            sum += __shfl_xor_sync(0xffffffffu, sum, off);
            sq  += __shfl_xor_sync(0xffffffffu, sq,  off);
        }
        float mean = sum * (1.0f / 256.0f);
        float var  = sq * (1.0f / 256.0f) - mean * mean;
        float r    = 1.0f / sqrtf(var + 1e-5f);
        float o[8];
        #pragma unroll
        for (int j = 0; j < 8; ++j)
            o[j] = wj[j] * ((acc[i][j] - mean) * r) + bj[j];
        float* op = out + ((size_t)b * HW_ + p) * C_;
        *(float4*)(op + cA) = make_float4(o[0], o[1], o[2], o[3]);
        *(float4*)(op + cB) = make_float4(o[4], o[5], o[6], o[7]);
    }
}

// ---------------- launcher ----------------
extern "C" void kernel_launch(void* const* d_in, const int* in_sizes, int n_in,
                              void* d_out, int out_size) {
    const float* x      = (const float*)d_in[0];
    const float* time_  = (const float*)d_in[1];
    const float* w_real = (const float*)d_in[2];
    const float* w_imag = (const float*)d_in[3];
    const float* conv_w = (const float*)d_in[4];
    const float* lin_w  = (const float*)d_in[5];
    const float* lin_b  = (const float*)d_in[6];
    const float* mlp_w1 = (const float*)d_in[7];
    const float* mlp_b1 = (const float*)d_in[8];
    const float* mlp_w2 = (const float*)d_in[9];
    const float* mlp_b2 = (const float*)d_in[10];
    const float* nww    = (const float*)d_in[11];
    const float* nwb    = (const float*)d_in[12];
    const float* nbw    = (const float*)d_in[13];
    const float* nbb    = (const float*)d_in[14];
    const float* kx     = (const float*)d_in[15];
    const float* ky     = (const float*)d_in[16];
    float* out = (float*)d_out;

    const int SM1 = 2 * 128 * 65 * 4 + 16 * 256 * 8 + 64 * 8;                  // 99,840
    const int SM4 = 128 * 129 * 4 + 2 * 128 * 65 * 4 + 16 * 256 * 8 + 64 * 8;  // 165,888
    cudaFuncSetAttribute(k_fwd, cudaFuncAttributeMaxDynamicSharedMemorySize, SM1);
    cudaFuncSetAttribute(k_inv, cudaFuncAttributeMaxDynamicSharedMemorySize, SM4);

    k_init<<<1, 256>>>(kx, ky);
    k_linT<<<dim3(8, 8), dim3(32, 8)>>>(lin_w);
    k_xT<<<dim3(512, 8, 4), dim3(32, 8)>>>(x);
    k_fwd<<<B_ * C_, 512, SM1>>>();
    k_gate<<<4, 256>>>(mlp_w1, mlp_b1, mlp_w2, mlp_b2);
    k_mix<<<dim3(130, 4, 4), 256>>>(w_real, w_imag);
    k_inv<<<B_ * C_, 512, SM4>>>(conv_w);
    k_specT<<<dim3(512, 8, 4), dim3(32, 8)>>>();
    k_out<<<dim3(256, 4), 256>>>(x, lin_b, time_, nww, nwb, nbw, nbb, out);
}

// round 7
// speedup vs baseline: 2.9653x; 1.0563x over previous
#include <cuda_runtime.h>
#include <math.h>

// ---------------- problem dims ----------------
#define B_    4
#define C_    256
#define RES_  128
#define HW_   16384
#define WF_   65
#define F_    8320       // 65*128, layout [k][u]  (idx = k*128 + u)
#define NB_   6

// ---------------- device scratch (allocation-free) ----------------
__device__ float  g_xT[B_*C_*HW_];        // (B,C,H,W)
__device__ float2 g_Xf[B_*C_*F_];         // forward spectrum  [k][u]
__device__ float2 g_Xmap[B_*C_*F_];       // channel-mixed low spectrum (mask region valid)
__device__ float  g_spec[B_*C_*HW_];      // irfft + conv, (B,C,HW)
__device__ float  g_specT[B_*C_*HW_];     // transposed to (B,HW,C)
__device__ float  g_bandsum[B_*C_*NB_];
__device__ float  g_alpha[B_*C_*NB_];
__device__ float  g_cnt[NB_];
__device__ int    g_mask[2];              // Ku (H thresh), Kw (W thresh)
__device__ float  g_linT[C_*C_];          // lin_w transposed: [d][c]
__device__ unsigned char g_bid[F_];       // band id table, [k][u]

// Exact float32 replica of the numpy radial band partition.
__device__ __forceinline__ int band_id(int u, int k) {
    float yy = __fdiv_rn((float)u, 127.0f);
    float xx = __fdiv_rn((float)k, 64.0f);
    float r  = __fsqrt_rn(__fadd_rn(__fmul_rn(yy, yy), __fmul_rn(xx, xx)));
    float den = __fadd_rn(__fsqrt_rn(2.0f), 1e-8f);
    r = __fdiv_rn(r, den);
    int b = (int)floorf(__fmul_rn(r, 6.0f));
    return b > 5 ? 5 : b;
}

// ---------------- register-resident 128-pt FFT, 4 pts/lane (j = lane + 32h) ----
// DIF, natural-order in, bit-reversed out: position p holds X[bitrev7(p)].
// sgn = -1 forward, +1 inverse (twiddle conjugation).

__device__ __forceinline__ float2 cmulf(float2 a, float2 b) {
    return make_float2(a.x * b.x - a.y * b.y, a.x * b.y + a.y * b.x);
}

struct Tw { float2 T1, T1b, T2, T16, T8, T4, T2b; };

__device__ __forceinline__ Tw make_tw(int lane, float sgn) {
    Tw t; float s, c;
    sincospif(lane * (1.0f / 64.0f), &s, &c);        t.T1  = make_float2(c, sgn * s);
    t.T1b = make_float2(-sgn * t.T1.y, sgn * t.T1.x);          // T1 * W^32
    sincospif(lane * (1.0f / 32.0f), &s, &c);        t.T2  = make_float2(c, sgn * s);
    sincospif((lane & 15) * (1.0f / 16.0f), &s, &c); t.T16 = make_float2(c, sgn * s);
    sincospif((lane & 7) * (1.0f / 8.0f), &s, &c);   t.T8  = make_float2(c, sgn * s);
    sincospif((lane & 3) * (1.0f / 4.0f), &s, &c);   t.T4  = make_float2(c, sgn * s);
    t.T2b = (lane & 1) ? make_float2(0.f, sgn) : make_float2(1.f, 0.f);
    return t;
}

__device__ __forceinline__ void bflyr(float2& a, float2& b, float2 tw) {
    float2 d = make_float2(a.x - b.x, a.y - b.y);
    a.x += b.x; a.y += b.y;
    b = cmulf(d, tw);
}

__device__ __forceinline__ void sstage(float2 v[4], int d, int lane, float2 tw) {
    bool hi = (lane & d) != 0;
#pragma unroll
    for (int h = 0; h < 4; ++h) {
        float ox = __shfl_xor_sync(0xffffffffu, v[h].x, d);
        float oy = __shfl_xor_sync(0xffffffffu, v[h].y, d);
        float sx_ = v[h].x + ox, sy_ = v[h].y + oy;
        float2 m = cmulf(make_float2(ox - v[h].x, oy - v[h].y), tw);
        v[h].x = hi ? m.x : sx_;
        v[h].y = hi ? m.y : sy_;
    }
}

__device__ __forceinline__ void fft128r(float2 v[4], int lane, const Tw& t) {
    bflyr(v[0], v[2], t.T1);    // stride 64
    bflyr(v[1], v[3], t.T1b);
    bflyr(v[0], v[1], t.T2);    // stride 32
    bflyr(v[2], v[3], t.T2);
    sstage(v, 16, lane, t.T16); // stride 16
    sstage(v, 8,  lane, t.T8);  // stride 8
    sstage(v, 4,  lane, t.T4);  // stride 4
    sstage(v, 2,  lane, t.T2b); // stride 2
    bool hi = lane & 1;         // stride 1, tw = 1
#pragma unroll
    for (int h = 0; h < 4; ++h) {
        float ox = __shfl_xor_sync(0xffffffffu, v[h].x, 1);
        float oy = __shfl_xor_sync(0xffffffffu, v[h].y, 1);
        v[h].x = hi ? ox - v[h].x : v[h].x + ox;
        v[h].y = hi ? oy - v[h].y : v[h].y + oy;
    }
}

// bank swizzle for the per-warp bitrev scatter buffer (conflict-free both ways)
#define SWZ(i) ((i) ^ (((i) >> 5) & 3))
__device__ __forceinline__ int br5(int x) { return (int)(__brev((unsigned)x) >> 27); }
__constant__ int c_br2[4] = {0, 2, 1, 3};

// scatter FFT result (bitrev positions) into warp-private ws, swizzled
__device__ __forceinline__ void fft_scatter(const float2 v[4], int lane,
                                            float* wsr, float* wsi) {
    int b5 = br5(lane);
#pragma unroll
    for (int h = 0; h < 4; ++h) {
        int idx = 4 * b5 + c_br2[h];
        int ph  = SWZ(idx);
        wsr[ph] = v[h].x;
        wsi[ph] = v[h].y;
    }
}

// ---------------- K0: counts + band table + mask dims ----------------
__global__ void k_init(const float* kx, const float* ky) {
    __shared__ int cnt[NB_];
    int t = threadIdx.x;
    if (t < NB_) cnt[t] = 0;
    __syncthreads();
    for (int idx = t; idx < F_; idx += blockDim.x) {
        int k = idx >> 7, u = idx & 127;
        int b = band_id(u, k);
        g_bid[idx] = (unsigned char)b;
        atomicAdd(&cnt[b], 1);
    }
    __syncthreads();
    if (t < NB_) g_cnt[t] = fmaxf((float)cnt[t], 1.0f);
    if (t == 0) {
        float sx = 1.0f / (1.0f + expf(-kx[0]));
        float sy = 1.0f / (1.0f + expf(-ky[0]));
        int Ku = (int)floorf(sx * 128.0f); Ku = Ku < 0 ? 0 : (Ku > 128 ? 128 : Ku);
        int Kw = (int)floorf(sy * 65.0f);  Kw = Kw < 0 ? 0 : (Kw > 65  ? 65  : Kw);
        g_mask[0] = Ku; g_mask[1] = Kw;
    }
}

// ---------------- K0b: transpose lin_w -> g_linT ----------------
__global__ void k_linT(const float* __restrict__ lw) {
    __shared__ float tile[32][33];
    int c0 = blockIdx.x * 32, d0 = blockIdx.y * 32;
    for (int i = threadIdx.y; i < 32; i += 8)
        tile[i][threadIdx.x] = lw[(c0 + i) * C_ + d0 + threadIdx.x];
    __syncthreads();
    for (int i = threadIdx.y; i < 32; i += 8)
        g_linT[(d0 + i) * C_ + c0 + threadIdx.x] = tile[threadIdx.x][i];
}

// ---------------- K_tr: x (B,HW,C) -> g_xT (B,C,HW) ----------------
__global__ void k_xT(const float* __restrict__ x) {
    __shared__ float tile[32][33];
    int p0 = blockIdx.x * 32, c0 = blockIdx.y * 32, b = blockIdx.z;
    const float* xb = x + (size_t)b * HW_ * C_;
    for (int i = threadIdx.y; i < 32; i += 8)
        tile[i][threadIdx.x] = xb[(size_t)(p0 + i) * C_ + c0 + threadIdx.x];
    __syncthreads();
    float* o = g_xT + (size_t)b * C_ * HW_;
    for (int i = threadIdx.y; i < 32; i += 8)
        o[(size_t)(c0 + i) * HW_ + p0 + threadIdx.x] = tile[threadIdx.x][i];
}

// ---------------- K1: forward rfft2 per (b,c) + band sums ----------------
// dyn smem: syTr[65*129] | syTi[65*129] | ws 16*256    = 83,464 B
__global__ void __launch_bounds__(512) k_fwd() {
    extern __shared__ float sm1[];
    float* syTr = sm1;                     // [k*129 + row]
    float* syTi = syTr + 65 * 129;
    float* wsall = syTi + 65 * 129;        // 16 warps * 256
    __shared__ float sbs[NB_];

    int tid = threadIdx.x, warp = tid >> 5, lane = tid & 31;
    Tw tw = make_tw(lane, -1.0f);
    if (tid < NB_) sbs[tid] = 0.0f;

    int bc = blockIdx.x;
    const float* img = g_xT + (size_t)bc * HW_;
    float* wsr = wsall + warp * 256;
    float* wsi = wsr + 128;

    // ---- row phase: pack 2 real rows -> 1 complex FFT, unpack half-spectra
    for (int rp = warp; rp < 64; rp += 16) {
        int ra = rp << 1, rb = ra + 1;
        const float* pa = img + ra * RES_;
        const float* pb = pa + RES_;
        float2 v[4];
#pragma unroll
        for (int h = 0; h < 4; ++h) {
            int j = lane + (h << 5);
            v[h] = make_float2(pa[j], pb[j]);
        }
        fft128r(v, lane, tw);
        fft_scatter(v, lane, wsr, wsi);
        __syncwarp();
#pragma unroll
        for (int h = 0; h < 3; ++h) {
            int k = lane + (h << 5);
            if (k <= 64) {
                int km = (128 - k) & 127;
                float zkr = wsr[SWZ(k)],  zki = wsi[SWZ(k)];
                float zmr = wsr[SWZ(km)], zmi = wsi[SWZ(km)];
                syTr[k * 129 + ra] = 0.5f * (zkr + zmr);
                syTi[k * 129 + ra] = 0.5f * (zki - zmi);
                syTr[k * 129 + rb] = 0.5f * (zki + zmi);
                syTi[k * 129 + rb] = 0.5f * (zmr - zkr);
            }
        }
        __syncwarp();
    }
    __syncthreads();

    // ---- column phase: 65 complex FFTs down the rows + band sums
    float acc6[NB_] = {0, 0, 0, 0, 0, 0};
    float2* outp = g_Xf + (size_t)bc * F_;
    for (int k = warp; k < 65; k += 16) {
        float2 v[4];
        const float* cr = syTr + k * 129;
        const float* ci = syTi + k * 129;
#pragma unroll
        for (int h = 0; h < 4; ++h) {
            int j = lane + (h << 5);
            v[h] = make_float2(cr[j], ci[j]);
        }
        fft128r(v, lane, tw);
        fft_scatter(v, lane, wsr, wsi);
        __syncwarp();
#pragma unroll
        for (int h = 0; h < 4; ++h) {
            int u = lane + (h << 5);
            float zr = wsr[SWZ(u)] * (1.0f / 128.0f);
            float zi = wsi[SWZ(u)] * (1.0f / 128.0f);
            outp[k * 128 + u] = make_float2(zr, zi);
            float mag = sqrtf(zr * zr + zi * zi);
            int bid = g_bid[k * 128 + u];
#pragma unroll
            for (int n = 0; n < NB_; ++n) acc6[n] += (bid == n) ? mag : 0.0f;
        }
        __syncwarp();
    }
#pragma unroll
    for (int n = 0; n < NB_; ++n) atomicAdd(&sbs[n], acc6[n]);
    __syncthreads();
    if (tid < NB_) g_bandsum[bc * NB_ + tid] = sbs[tid];
}

// ---------------- K2: gate MLP (one thread per (b,c)) ----------------
__global__ void k_gate(const float* __restrict__ w1, const float* __restrict__ b1,
                       const float* __restrict__ w2, const float* __restrict__ b2) {
    int bc = blockIdx.x * blockDim.x + threadIdx.x;
    if (bc >= B_ * C_) return;
    float means[NB_];
    #pragma unroll
    for (int n = 0; n < NB_; ++n)
        means[n] = g_bandsum[bc * NB_ + n] / (g_cnt[n] + 1e-6f);
    float acc[NB_] = {0, 0, 0, 0, 0, 0};
    for (int j = 0; j < 128; ++j) {
        float h = b1[j];
        #pragma unroll
        for (int n = 0; n < NB_; ++n) h += means[n] * w1[j * NB_ + n];
        h = fmaxf(h, 0.0f);
        #pragma unroll
        for (int n = 0; n < NB_; ++n) acc[n] += w2[n * 128 + j] * h;
    }
    #pragma unroll
    for (int n = 0; n < NB_; ++n)
        g_alpha[bc * NB_ + n] = 1.0f / (1.0f + expf(-(acc[n] + b2[n])));
}

// ---------------- K3: complex channel-mix GEMM over masked freqs ----------------
__global__ void __launch_bounds__(256) k_mix(const float* __restrict__ wr,
                                             const float* __restrict__ wi) {
    __shared__ float swr[16][64], swi[16][64], sxr[16][64], sxi[16][64];
    int Ku = g_mask[0], Kw = g_mask[1];
    int Fm = Ku * Kw;
    int fm0 = blockIdx.x * 64;
    if (fm0 >= Fm) return;
    int c0 = blockIdx.y * 64;
    int b  = blockIdx.z;
    int tid = threadIdx.x;
    int cg = tid >> 4, fg = tid & 15;

    float ar[4][4], ai[4][4];
    #pragma unroll
    for (int j = 0; j < 4; ++j)
        #pragma unroll
        for (int i = 0; i < 4; ++i) { ar[j][i] = 0.f; ai[j][i] = 0.f; }

    int cl = tid >> 2, q = tid & 3;
    int ddl = tid >> 4; int f4 = (tid & 15) * 4;

    int midx[4]; bool mok[4];
    #pragma unroll
    for (int ii = 0; ii < 4; ++ii) {
        int fm = fm0 + f4 + ii;
        mok[ii] = fm < Fm;
        if (mok[ii]) {
            int k = fm / Ku, u = fm - k * Ku;
            midx[ii] = k * 128 + u;
        } else midx[ii] = 0;
    }

    for (int d0 = 0; d0 < C_; d0 += 16) {
        float4 vr = *(const float4*)(wr + (size_t)(c0 + cl) * C_ + d0 + q * 4);
        float4 vi = *(const float4*)(wi + (size_t)(c0 + cl) * C_ + d0 + q * 4);
        swr[q * 4 + 0][cl] = vr.x; swr[q * 4 + 1][cl] = vr.y;
        swr[q * 4 + 2][cl] = vr.z; swr[q * 4 + 3][cl] = vr.w;
        swi[q * 4 + 0][cl] = vi.x; swi[q * 4 + 1][cl] = vi.y;
        swi[q * 4 + 2][cl] = vi.z; swi[q * 4 + 3][cl] = vi.w;
        const float2* xrow = g_Xf + (size_t)(b * C_ + d0 + ddl) * F_;
        #pragma unroll
        for (int ii = 0; ii < 4; ++ii) {
            float2 z = mok[ii] ? xrow[midx[ii]] : make_float2(0.f, 0.f);
            sxr[ddl][f4 + ii] = z.x;
            sxi[ddl][f4 + ii] = z.y;
        }
        __syncthreads();
        #pragma unroll
        for (int dd = 0; dd < 16; ++dd) {
            float4 w4r = *(const float4*)&swr[dd][cg * 4];
            float4 w4i = *(const float4*)&swi[dd][cg * 4];
            float4 x4r = *(const float4*)&sxr[dd][fg * 4];
            float4 x4i = *(const float4*)&sxi[dd][fg * 4];
            float wrv[4] = {w4r.x, w4r.y, w4r.z, w4r.w};
            float wiv[4] = {w4i.x, w4i.y, w4i.z, w4i.w};
            float xrv[4] = {x4r.x, x4r.y, x4r.z, x4r.w};
            float xiv[4] = {x4i.x, x4i.y, x4i.z, x4i.w};
            #pragma unroll
            for (int j = 0; j < 4; ++j)
                #pragma unroll
                for (int i = 0; i < 4; ++i) {
                    ar[j][i] += wrv[j] * xrv[i] - wiv[j] * xiv[i];
                    ai[j][i] += wrv[j] * xiv[i] + wiv[j] * xrv[i];
                }
        }
        __syncthreads();
    }
    #pragma unroll
    for (int j = 0; j < 4; ++j) {
        int c = c0 + cg * 4 + j;
        float2* orow = g_Xmap + (size_t)(b * C_ + c) * F_;
        #pragma unroll
        for (int i = 0; i < 4; ++i) {
            int fm = fm0 + fg * 4 + i;
            if (fm < Fm) {
                int k = fm / Ku, u = fm - k * Ku;
                orow[k * 128 + u] = make_float2(ar[j][i], ai[j][i]);
            }
        }
    }
}

// ---------------- K4: fuse + irfft2 + depthwise conv per (b,c) ----------------
// dyn smem: sx[128*129] | syhr[128*65] | syhi[128*65] | ws 32*256 = 165,376 B
__global__ void __launch_bounds__(1024, 1) k_inv(const float* __restrict__ conv_w) {
    extern __shared__ float sm4[];
    float* sx   = sm4;                     // 128*129 (image for conv)
    float* syhr = sx + 128 * 129;          // [h*65 + k]
    float* syhi = syhr + 128 * 65;
    float* wsall = syhi + 128 * 65;        // 32 warps * 256
    __shared__ float sal[NB_];

    int tid = threadIdx.x, warp = tid >> 5, lane = tid & 31;
    int bc  = blockIdx.x;
    int c   = bc & 255;
    Tw tw = make_tw(lane, 1.0f);           // inverse twiddles

    if (tid < NB_) sal[tid] = g_alpha[bc * NB_ + tid];

    float cw[9];
    #pragma unroll
    for (int j = 0; j < 9; ++j) cw[j] = conv_w[c * 9 + j];

    const float* img = g_xT + (size_t)bc * HW_;
    for (int i = tid; i < HW_; i += 1024) {
        int r = i >> 7, w = i & 127;
        sx[r * 129 + w] = img[i];
    }
    __syncthreads();

    int Ku = g_mask[0], Kw = g_mask[1];
    const float2* Xf = g_Xf   + (size_t)bc * F_;
    const float2* Xm = g_Xmap + (size_t)bc * F_;
    float* wsr = wsall + warp * 256;
    float* wsi = wsr + 128;

    // ---- column inverse: fuse alpha/mask on load, inverse FFT down rows
    for (int k = warp; k < 65; k += 32) {
        bool kin = (k < Kw);
        float2 v[4];
#pragma unroll
        for (int h = 0; h < 4; ++h) {
            int u = lane + (h << 5);
            int idx = k * 128 + u;
            float a = sal[g_bid[idx]];
            if (kin && u < Ku) {
                float2 m = Xm[idx];
                v[h] = make_float2(a * m.x, a * m.y);
            } else {
                float2 z = Xf[idx];
                float om = 1.0f - a;
                v[h] = make_float2(om * z.x, om * z.y);
            }
        }
        fft128r(v, lane, tw);
        // scatter: position p holds y[bitrev(p)] -> syh[bitrev(p)*65 + k]
        int b5 = br5(lane);
#pragma unroll
        for (int h = 0; h < 4; ++h) {
            int hh = 4 * b5 + c_br2[h];
            syhr[hh * 65 + k] = v[h].x;
            syhi[hh * 65 + k] = v[h].y;
        }
    }
    __syncthreads();

    // ---- row inverse: Hermitian-pack + inverse FFT + conv
    float* outp = g_spec + (size_t)bc * HW_;
    for (int rp = warp; rp < 64; rp += 32) {
        int ra = rp << 1, rb = ra + 1;
        const float* yar_ = syhr + ra * 65; const float* yai_ = syhi + ra * 65;
        const float* ybr_ = syhr + rb * 65; const float* ybi_ = syhi + rb * 65;
        float2 v[4];
#pragma unroll
        for (int h = 0; h < 4; ++h) {
            int j = lane + (h << 5);
            float2 z;
            if (j == 0) {
                z = make_float2(yar_[0], ybr_[0]);
            } else if (j == 64) {
                z = make_float2(yar_[64], ybr_[64]);
            } else if (j < 64) {
                z = make_float2(yar_[j] - ybi_[j], yai_[j] + ybr_[j]);
            } else {
                int k = 128 - j;
                z = make_float2(yar_[k] + ybi_[k], ybr_[k] - yai_[k]);
            }
            v[h] = z;
        }
        fft128r(v, lane, tw);
        fft_scatter(v, lane, wsr, wsi);
        __syncwarp();
#pragma unroll
        for (int h = 0; h < 4; ++h) {
            int w = lane + (h << 5);
            float va = wsr[SWZ(w)] * (1.0f / 128.0f);
            float vb = wsi[SWZ(w)] * (1.0f / 128.0f);
            float cva = 0.f, cvb = 0.f;
            #pragma unroll
            for (int di = -1; di <= 1; ++di) {
                #pragma unroll
                for (int dj = -1; dj <= 1; ++dj) {
                    int ww = w + dj;
                    if (ww < 0 || ww >= 128) continue;
                    float cwv = cw[(di + 1) * 3 + (dj + 1)];
                    int ha = ra + di;
                    if (ha >= 0 && ha < 128) cva += sx[ha * 129 + ww] * cwv;
                    int hb = rb + di;
                    if (hb >= 0 && hb < 128) cvb += sx[hb * 129 + ww] * cwv;
                }
            }
            outp[ra * 128 + w] = va + cva;
            outp[rb * 128 + w] = vb + cvb;
        }
        __syncwarp();
    }
}

// ---------------- K4b: g_spec (B,C,HW) -> g_specT (B,HW,C) ----------------
__global__ void k_specT() {
    __shared__ float tile[32][33];
    int p0 = blockIdx.x * 32, c0 = blockIdx.y * 32, b = blockIdx.z;
    for (int i = threadIdx.y; i < 32; i += 8)
        tile[i][threadIdx.x] = g_spec[(size_t)(b * C_ + c0 + i) * HW_ + p0 + threadIdx.x];
    __syncthreads();
    for (int i = threadIdx.y; i < 32; i += 8)
        g_specT[((size_t)b * HW_ + p0 + i) * C_ + c0 + threadIdx.x] = tile[threadIdx.x][i];
}

// ---------------- K5: pointwise GEMM + adds + conditional LN ----------------
__global__ void __launch_bounds__(256) k_out(
    const float* __restrict__ x, const float* __restrict__ lin_b,
    const float* __restrict__ time_, const float* __restrict__ nww,
    const float* __restrict__ nwb, const float* __restrict__ nbw,
    const float* __restrict__ nbb, float* __restrict__ out) {
    __shared__ float sa[16 * 64];
    __shared__ float sb[16 * 256];
    int b = blockIdx.y;
    int p0 = blockIdx.x * 64;
    int tid = threadIdx.x;
    int pg = tid >> 5;
    int cg = tid & 31;

    float acc[8][8];
    #pragma unroll
    for (int i = 0; i < 8; ++i)
        #pragma unroll
        for (int j = 0; j < 8; ++j) acc[i][j] = 0.f;

    const float* xb = x + ((size_t)b * HW_ + p0) * C_;
    int arow = tid >> 2, aq = tid & 3;

    for (int d0 = 0; d0 < C_; d0 += 16) {
        float4 v = *(const float4*)(xb + (size_t)arow * C_ + d0 + aq * 4);
        sa[(aq * 4 + 0) * 64 + arow] = v.x;
        sa[(aq * 4 + 1) * 64 + arow] = v.y;
        sa[(aq * 4 + 2) * 64 + arow] = v.z;
        sa[(aq * 4 + 3) * 64 + arow] = v.w;
        const float4* src = (const float4*)(g_linT + (size_t)d0 * C_);
        float4* dst = (float4*)sb;
        #pragma unroll
        for (int q = 0; q < 4; ++q) dst[tid * 4 + q] = src[tid * 4 + q];
        __syncthreads();
        #pragma unroll
        for (int dd = 0; dd < 16; ++dd) {
            float4 a0 = *(const float4*)(sa + dd * 64 + pg * 8);
            float4 a1 = *(const float4*)(sa + dd * 64 + pg * 8 + 4);
            float4 b0 = *(const float4*)(sb + dd * 256 + cg * 4);
            float4 b1 = *(const float4*)(sb + dd * 256 + 128 + cg * 4);
            float av[8] = {a0.x, a0.y, a0.z, a0.w, a1.x, a1.y, a1.z, a1.w};
            float bv[8] = {b0.x, b0.y, b0.z, b0.w, b1.x, b1.y, b1.z, b1.w};
            #pragma unroll
            for (int i = 0; i < 8; ++i)
                #pragma unroll
                for (int j = 0; j < 8; ++j) acc[i][j] += av[i] * bv[j];
        }
        __syncthreads();
    }

    int cA = cg * 4, cB = 128 + cg * 4;
    float tb = time_[b];
    float lb[8], wj[8], bj[8];
    #pragma unroll
    for (int j = 0; j < 8; ++j) {
        int cc = (j < 4) ? (cA + j) : (cB + j - 4);
        lb[j] = lin_b[cc];
        wj[j] = tb * nww[cc] + nwb[cc];
        bj[j] = tb * nbw[cc] + nbb[cc];
    }

    #pragma unroll
    for (int i = 0; i < 8; ++i) {
        int p = p0 + pg * 8 + i;
        const float* sp = g_specT + ((size_t)b * HW_ + p) * C_;
        float4 s0 = *(const float4*)(sp + cA);
        float4 s1 = *(const float4*)(sp + cB);
        float sv[8] = {s0.x, s0.y, s0.z, s0.w, s1.x, s1.y, s1.z, s1.w};
        float sum = 0.f, sq = 0.f;
        #pragma unroll
        for (int j = 0; j < 8; ++j) {
            acc[i][j] += lb[j] + sv[j];
            sum += acc[i][j];
            sq  += acc[i][j] * acc[i][j];
        }
        #pragma unroll
        for (int off = 16; off > 0; off >>= 1) {
            sum += __shfl_xor_sync(0xffffffffu, sum, off);
            sq  += __shfl_xor_sync(0xffffffffu, sq,  off);
        }
        float mean = sum * (1.0f / 256.0f);
        float var  = sq * (1.0f / 256.0f) - mean * mean;
        float r    = 1.0f / sqrtf(var + 1e-5f);
        float o[8];
        #pragma unroll
        for (int j = 0; j < 8; ++j)
            o[j] = wj[j] * ((acc[i][j] - mean) * r) + bj[j];
        float* op = out + ((size_t)b * HW_ + p) * C_;
        *(float4*)(op + cA) = make_float4(o[0], o[1], o[2], o[3]);
        *(float4*)(op + cB) = make_float4(o[4], o[5], o[6], o[7]);
    }
}

// ---------------- launcher ----------------
extern "C" void kernel_launch(void* const* d_in, const int* in_sizes, int n_in,
                              void* d_out, int out_size) {
    const float* x      = (const float*)d_in[0];
    const float* time_  = (const float*)d_in[1];
    const float* w_real = (const float*)d_in[2];
    const float* w_imag = (const float*)d_in[3];
    const float* conv_w = (const float*)d_in[4];
    const float* lin_w  = (const float*)d_in[5];
    const float* lin_b  = (const float*)d_in[6];
    const float* mlp_w1 = (const float*)d_in[7];
    const float* mlp_b1 = (const float*)d_in[8];
    const float* mlp_w2 = (const float*)d_in[9];
    const float* mlp_b2 = (const float*)d_in[10];
    const float* nww    = (const float*)d_in[11];
    const float* nwb    = (const float*)d_in[12];
    const float* nbw    = (const float*)d_in[13];
    const float* nbb    = (const float*)d_in[14];
    const float* kx     = (const float*)d_in[15];
    const float* ky     = (const float*)d_in[16];
    float* out = (float*)d_out;

    const int SM1 = 2 * 65 * 129 * 4 + 16 * 256 * 4;                  // 83,464
    const int SM4 = 128 * 129 * 4 + 2 * 128 * 65 * 4 + 32 * 256 * 4;  // 165,376
    cudaFuncSetAttribute(k_fwd, cudaFuncAttributeMaxDynamicSharedMemorySize, SM1);
    cudaFuncSetAttribute(k_inv, cudaFuncAttributeMaxDynamicSharedMemorySize, SM4);

    k_init<<<1, 256>>>(kx, ky);
    k_linT<<<dim3(8, 8), dim3(32, 8)>>>(lin_w);
    k_xT<<<dim3(512, 8, 4), dim3(32, 8)>>>(x);
    k_fwd<<<B_ * C_, 512, SM1>>>();
    k_gate<<<4, 256>>>(mlp_w1, mlp_b1, mlp_w2, mlp_b2);
    k_mix<<<dim3(130, 4, 4), 256>>>(w_real, w_imag);
    k_inv<<<B_ * C_, 1024, SM4>>>(conv_w);
    k_specT<<<dim3(512, 8, 4), dim3(32, 8)>>>();
    k_out<<<dim3(256, 4), 256>>>(x, lin_b, time_, nww, nwb, nbw, nbb, out);
}